// round 1
// baseline (speedup 1.0000x reference)
#include <cuda_runtime.h>
#include <math.h>

#define BSZ   32
#define NT    196
#define DV    1024
#define NBOX  512
#define GRID_ 14
#define MAXATT 9
#define NLAB  20

#define Y_OFF   0
#define L_OFF   (NBOX * DV)              // 524288
#define D_OFF   (L_OFF + NBOX * MAXATT)  // 528896

__constant__ int c_id2cat[NLAB] = {3,5,2,4,6,3,7,2,5,4,8,3,2,6,5,4,3,9,2,5};

__device__ float g_pooled[NBOX * DV];
__device__ float g_h[NBOX * DV];

// ---------------------------------------------------------------------------
// Kernel A: ROI 1x1 max pool. One block per box, 256 threads, float4/thread.
// ---------------------------------------------------------------------------
__global__ __launch_bounds__(256) void roi_pool_kernel(
    const float* __restrict__ x, const float* __restrict__ boxes)
{
    const int n   = blockIdx.x;
    const int tid = threadIdx.x;

    const float SC = 14.0f / 224.0f;
    float b0 = boxes[n * 5 + 0];
    float fx1 = boxes[n * 5 + 1];
    float fy1 = boxes[n * 5 + 2];
    float fx2 = boxes[n * 5 + 3];
    float fy2 = boxes[n * 5 + 4];
    int bidx = (int)b0;
    int cx1 = (int)floorf(fx1 * SC + 0.5f);
    int cy1 = (int)floorf(fy1 * SC + 0.5f);
    int cx2 = (int)floorf(fx2 * SC + 0.5f);
    int cy2 = (int)floorf(fy2 * SC + 0.5f);

    int hs = min(max(cy1, 0), GRID_);
    int he = min(max(max(cy2 + 1, cy1 + 1), 0), GRID_);
    int ws = min(max(cx1, 0), GRID_);
    int we = min(max(max(cx2 + 1, cx1 + 1), 0), GRID_);

    float4* dst = (float4*)(g_pooled + (size_t)n * DV);

    if (hs >= he || ws >= we) {
        dst[tid] = make_float4(0.f, 0.f, 0.f, 0.f);
        return;
    }

    const float4* xb = (const float4*)(x + (size_t)bidx * NT * DV);
    float4 mx = make_float4(-INFINITY, -INFINITY, -INFINITY, -INFINITY);
    for (int h = hs; h < he; ++h) {
        for (int w = ws; w < we; ++w) {
            float4 v = xb[(h * GRID_ + w) * (DV / 4) + tid];
            mx.x = fmaxf(mx.x, v.x);
            mx.y = fmaxf(mx.y, v.y);
            mx.z = fmaxf(mx.z, v.z);
            mx.w = fmaxf(mx.w, v.w);
        }
    }
    dst[tid] = mx;
}

// ---------------------------------------------------------------------------
// Kernel B: h = pooled @ W_ff^T + b_ff   (M=512, N=1024, K=1024, fp32)
// 64x64 block tile, BK=16, 256 threads, 4x4 microtile, padded smem.
// ---------------------------------------------------------------------------
#define BM 64
#define BN 64
#define BK 16

__global__ __launch_bounds__(256) void sgemm_kernel(
    const float* __restrict__ W, const float* __restrict__ bias)
{
    __shared__ __align__(16) float As[BK][BM + 4];
    __shared__ __align__(16) float Bs[BK][BN + 4];

    const int t  = threadIdx.x;
    const int tx = t & 15;       // 0..15 -> n
    const int ty = t >> 4;       // 0..15 -> m
    const int bx = blockIdx.x;   // n tile
    const int by = blockIdx.y;   // m tile

    const float* A = g_pooled + (size_t)(by * BM) * DV;
    const float* B = W        + (size_t)(bx * BN) * DV;

    const int lr = t >> 2;         // 0..63 row within tile
    const int lk = (t & 3) * 4;    // 0,4,8,12 k offset

    float acc[4][4] = {};

    for (int k0 = 0; k0 < DV; k0 += BK) {
        float4 av = *(const float4*)(A + (size_t)lr * DV + k0 + lk);
        float4 bv = *(const float4*)(B + (size_t)lr * DV + k0 + lk);
        As[lk + 0][lr] = av.x; As[lk + 1][lr] = av.y;
        As[lk + 2][lr] = av.z; As[lk + 3][lr] = av.w;
        Bs[lk + 0][lr] = bv.x; Bs[lk + 1][lr] = bv.y;
        Bs[lk + 2][lr] = bv.z; Bs[lk + 3][lr] = bv.w;
        __syncthreads();

        #pragma unroll
        for (int kk = 0; kk < BK; ++kk) {
            float4 a = *(const float4*)&As[kk][ty * 4];
            float4 b = *(const float4*)&Bs[kk][tx * 4];
            acc[0][0] += a.x * b.x; acc[0][1] += a.x * b.y;
            acc[0][2] += a.x * b.z; acc[0][3] += a.x * b.w;
            acc[1][0] += a.y * b.x; acc[1][1] += a.y * b.y;
            acc[1][2] += a.y * b.z; acc[1][3] += a.y * b.w;
            acc[2][0] += a.z * b.x; acc[2][1] += a.z * b.y;
            acc[2][2] += a.z * b.z; acc[2][3] += a.z * b.w;
            acc[3][0] += a.w * b.x; acc[3][1] += a.w * b.y;
            acc[3][2] += a.w * b.z; acc[3][3] += a.w * b.w;
        }
        __syncthreads();
    }

    #pragma unroll
    for (int i = 0; i < 4; ++i) {
        int m = by * BM + ty * 4 + i;
        #pragma unroll
        for (int j = 0; j < 4; ++j) {
            int nn = bx * BN + tx * 4 + j;
            g_h[(size_t)m * DV + nn] = acc[i][j] + bias[nn];
        }
    }
}

// ---------------------------------------------------------------------------
// Kernel C: LayerNorm + exact GELU + heads. One block (256 thr) per box row.
// ---------------------------------------------------------------------------
__device__ __forceinline__ float warp_sum(float v) {
    v += __shfl_xor_sync(0xffffffff, v, 16);
    v += __shfl_xor_sync(0xffffffff, v, 8);
    v += __shfl_xor_sync(0xffffffff, v, 4);
    v += __shfl_xor_sync(0xffffffff, v, 2);
    v += __shfl_xor_sync(0xffffffff, v, 1);
    return v;
}

__global__ __launch_bounds__(256) void epilogue_kernel(
    const float* __restrict__ ln_g, const float* __restrict__ ln_b,
    const int*   __restrict__ labels,
    const float* __restrict__ Wh, const float* __restrict__ bh,
    const float* __restrict__ Wd, const float* __restrict__ bd,
    float* __restrict__ out)
{
    __shared__ float sred[8];
    __shared__ float red10[10][8];

    const int r    = blockIdx.x;
    const int tid  = threadIdx.x;
    const int lane = tid & 31;
    const int wid  = tid >> 5;
    const int d    = tid * 4;

    float4 hv = *(const float4*)(g_h + (size_t)r * DV + d);

    // mean
    float s = warp_sum(hv.x + hv.y + hv.z + hv.w);
    if (lane == 0) sred[wid] = s;
    __syncthreads();
    float tot = 0.f;
    #pragma unroll
    for (int i = 0; i < 8; ++i) tot += sred[i];
    const float mu = tot * (1.0f / DV);
    __syncthreads();

    // variance (two-pass, centered)
    float cx = hv.x - mu, cy = hv.y - mu, cz = hv.z - mu, cw = hv.w - mu;
    float s2 = warp_sum(cx * cx + cy * cy + cz * cz + cw * cw);
    if (lane == 0) sred[wid] = s2;
    __syncthreads();
    float tot2 = 0.f;
    #pragma unroll
    for (int i = 0; i < 8; ++i) tot2 += sred[i];
    const float rstd = rsqrtf(tot2 * (1.0f / DV) + 1e-5f);

    float4 g4 = *(const float4*)(ln_g + d);
    float4 b4 = *(const float4*)(ln_b + d);
    float4 y4;
    y4.x = cx * rstd * g4.x + b4.x;
    y4.y = cy * rstd * g4.y + b4.y;
    y4.z = cz * rstd * g4.z + b4.z;
    y4.w = cw * rstd * g4.w + b4.w;

    // exact GELU: x * 0.5 * (1 + erf(x / sqrt(2)))
    const float IS2 = 0.70710678118654752f;
    y4.x = y4.x * 0.5f * (1.0f + erff(y4.x * IS2));
    y4.y = y4.y * 0.5f * (1.0f + erff(y4.y * IS2));
    y4.z = y4.z * 0.5f * (1.0f + erff(y4.z * IS2));
    y4.w = y4.w * 0.5f * (1.0f + erff(y4.w * IS2));

    *(float4*)(out + Y_OFF + (size_t)r * DV + d) = y4;

    // heads: 9 attribute dots + 1 discriminator dot
    const int lab  = labels[r];
    const int ncat = c_id2cat[lab];
    const float* whp = Wh + (size_t)lab * MAXATT * DV;

    float p[10];
    #pragma unroll
    for (int k = 0; k < MAXATT; ++k) {
        float4 w4 = *(const float4*)(whp + (size_t)k * DV + d);
        p[k] = y4.x * w4.x + y4.y * w4.y + y4.z * w4.z + y4.w * w4.w;
    }
    {
        float4 w4 = *(const float4*)(Wd + d);
        p[9] = y4.x * w4.x + y4.y * w4.y + y4.z * w4.z + y4.w * w4.w;
    }

    __syncthreads();   // protect sred/red10 reuse ordering
    #pragma unroll
    for (int i = 0; i < 10; ++i) {
        float v = warp_sum(p[i]);
        if (lane == 0) red10[i][wid] = v;
    }
    __syncthreads();

    if (tid < 10) {
        float t2 = 0.f;
        #pragma unroll
        for (int i = 0; i < 8; ++i) t2 += red10[tid][i];
        if (tid < MAXATT) {
            float lv = (tid < ncat) ? (t2 + bh[lab * MAXATT + tid]) : 0.0f;
            out[L_OFF + r * MAXATT + tid] = lv;
        } else {
            out[D_OFF + r] = t2 + bd[0];
        }
    }
}

// ---------------------------------------------------------------------------
extern "C" void kernel_launch(void* const* d_in, const int* in_sizes, int n_in,
                              void* d_out, int out_size)
{
    const float* x      = (const float*)d_in[0];
    const float* boxes  = (const float*)d_in[1];
    const int*   labels = (const int*)  d_in[2];
    const float* W_ff   = (const float*)d_in[3];
    const float* b_ff   = (const float*)d_in[4];
    const float* ln_g   = (const float*)d_in[5];
    const float* ln_b   = (const float*)d_in[6];
    const float* Wh     = (const float*)d_in[7];
    const float* bh     = (const float*)d_in[8];
    const float* Wd     = (const float*)d_in[9];
    const float* bd     = (const float*)d_in[10];
    float* out = (float*)d_out;

    roi_pool_kernel<<<NBOX, 256>>>(x, boxes);

    dim3 gg(DV / BN, NBOX / BM);   // 16 x 8 = 128 blocks
    sgemm_kernel<<<gg, 256>>>(W_ff, b_ff);

    epilogue_kernel<<<NBOX, 256>>>(ln_g, ln_b, labels, Wh, bh, Wd, bd, out);
}

// round 2
// speedup vs baseline: 1.6706x; 1.6706x over previous
#include <cuda_runtime.h>
#include <math.h>
#include <stdint.h>

#define BSZ   32
#define NT    196
#define DV    1024
#define NBOX  512
#define GRID_ 14
#define MAXATT 9
#define NLAB  20

#define Y_OFF   0
#define L_OFF   (NBOX * DV)              // 524288
#define D_OFF   (L_OFF + NBOX * MAXATT)  // 528896

__constant__ int c_id2cat[NLAB] = {3,5,2,4,6,3,7,2,5,4,8,3,2,6,5,4,3,9,2,5};

__device__ float g_pooled[NBOX * DV];
__device__ float g_h[NBOX * DV];

// ---------------------------------------------------------------------------
// Kernel A: ROI 1x1 max pool. One block per box, 256 threads, float4/thread.
// ---------------------------------------------------------------------------
__global__ __launch_bounds__(256) void roi_pool_kernel(
    const float* __restrict__ x, const float* __restrict__ boxes)
{
    const int n   = blockIdx.x;
    const int tid = threadIdx.x;

    const float SC = 14.0f / 224.0f;
    float b0 = boxes[n * 5 + 0];
    float fx1 = boxes[n * 5 + 1];
    float fy1 = boxes[n * 5 + 2];
    float fx2 = boxes[n * 5 + 3];
    float fy2 = boxes[n * 5 + 4];
    int bidx = (int)b0;
    int cx1 = (int)floorf(fx1 * SC + 0.5f);
    int cy1 = (int)floorf(fy1 * SC + 0.5f);
    int cx2 = (int)floorf(fx2 * SC + 0.5f);
    int cy2 = (int)floorf(fy2 * SC + 0.5f);

    int hs = min(max(cy1, 0), GRID_);
    int he = min(max(max(cy2 + 1, cy1 + 1), 0), GRID_);
    int ws = min(max(cx1, 0), GRID_);
    int we = min(max(max(cx2 + 1, cx1 + 1), 0), GRID_);

    float4* dst = (float4*)(g_pooled + (size_t)n * DV);

    if (hs >= he || ws >= we) {
        dst[tid] = make_float4(0.f, 0.f, 0.f, 0.f);
        return;
    }

    const float4* xb = (const float4*)(x + (size_t)bidx * NT * DV);
    float4 mx = make_float4(-INFINITY, -INFINITY, -INFINITY, -INFINITY);
    for (int h = hs; h < he; ++h) {
        for (int w = ws; w < we; ++w) {
            float4 v = xb[(h * GRID_ + w) * (DV / 4) + tid];
            mx.x = fmaxf(mx.x, v.x);
            mx.y = fmaxf(mx.y, v.y);
            mx.z = fmaxf(mx.z, v.z);
            mx.w = fmaxf(mx.w, v.w);
        }
    }
    dst[tid] = mx;
}

// ---------------------------------------------------------------------------
// Kernel B: h = pooled @ W_ff^T + b_ff   (M=512, N=1024, K=1024)
// 3xTF32 mma.sync.m16n8k8 tensor-core GEMM.
// 64x64 block tile, BK=32, 128 threads (4 warps, 32x32 warp tiles),
// double-buffered smem (stride 36, conflict-free), register prefetch.
// ---------------------------------------------------------------------------
#define BK 32
#define SSTR 36

__device__ __forceinline__ uint32_t f2tf(float x) {
    uint32_t r;
    asm("cvt.rna.tf32.f32 %0, %1;" : "=r"(r) : "f"(x));
    return r;
}

__device__ __forceinline__ void mma_tf32(float c[4], const uint32_t a[4], const uint32_t b[2]) {
    asm volatile(
        "mma.sync.aligned.m16n8k8.row.col.f32.tf32.tf32.f32 "
        "{%0,%1,%2,%3}, {%4,%5,%6,%7}, {%8,%9}, {%0,%1,%2,%3};\n"
        : "+f"(c[0]), "+f"(c[1]), "+f"(c[2]), "+f"(c[3])
        : "r"(a[0]), "r"(a[1]), "r"(a[2]), "r"(a[3]), "r"(b[0]), "r"(b[1]));
}

__global__ __launch_bounds__(128) void gemm_tf32_kernel(
    const float* __restrict__ W, const float* __restrict__ bias)
{
    __shared__ float As[2][64][SSTR];
    __shared__ float Bs[2][64][SSTR];

    const int tid  = threadIdx.x;
    const int lane = tid & 31;
    const int wid  = tid >> 5;
    const int wm   = (wid & 1) * 32;   // warp M offset within tile
    const int wn   = (wid >> 1) * 32;  // warp N offset within tile

    const float* Ag = g_pooled + (size_t)(blockIdx.y * 64) * DV;
    const float* Bg = W        + (size_t)(blockIdx.x * 64) * DV;

    float4 ra[4], rb[4];

    // --- gmem -> regs ---
    #define LD_TILES(K0)                                                     \
        {                                                                    \
            _Pragma("unroll")                                                \
            for (int i = 0; i < 4; ++i) {                                    \
                int p = tid + i * 128;                                       \
                int row = p >> 3;                                            \
                int kq  = (p & 7) * 4;                                       \
                ra[i] = *(const float4*)(Ag + (size_t)row * DV + (K0) + kq); \
                rb[i] = *(const float4*)(Bg + (size_t)row * DV + (K0) + kq); \
            }                                                                \
        }

    // --- regs -> smem ---
    #define ST_TILES(S)                                                      \
        {                                                                    \
            _Pragma("unroll")                                                \
            for (int i = 0; i < 4; ++i) {                                    \
                int p = tid + i * 128;                                       \
                int row = p >> 3;                                            \
                int kq  = (p & 7) * 4;                                       \
                *(float4*)&As[S][row][kq] = ra[i];                           \
                *(float4*)&Bs[S][row][kq] = rb[i];                           \
            }                                                                \
        }

    float c[2][4][4] = {};

    LD_TILES(0);
    ST_TILES(0);
    __syncthreads();
    LD_TILES(BK);

    const int kk = lane & 3;
    const int gp = lane >> 2;

    for (int it = 0; it < DV / BK; ++it) {
        const int s = it & 1;

        #pragma unroll
        for (int ks = 0; ks < 4; ++ks) {
            const int kb = ks * 8;

            uint32_t ah[2][4], al[2][4];
            #pragma unroll
            for (int mm = 0; mm < 2; ++mm) {
                int m = wm + mm * 16 + gp;
                float a0 = As[s][m][kb + kk];
                float a1 = As[s][m + 8][kb + kk];
                float a2 = As[s][m][kb + kk + 4];
                float a3 = As[s][m + 8][kb + kk + 4];
                ah[mm][0] = f2tf(a0); al[mm][0] = __float_as_uint(a0 - __uint_as_float(ah[mm][0]));
                ah[mm][1] = f2tf(a1); al[mm][1] = __float_as_uint(a1 - __uint_as_float(ah[mm][1]));
                ah[mm][2] = f2tf(a2); al[mm][2] = __float_as_uint(a2 - __uint_as_float(ah[mm][2]));
                ah[mm][3] = f2tf(a3); al[mm][3] = __float_as_uint(a3 - __uint_as_float(ah[mm][3]));
            }

            uint32_t bh_[4][2], bl_[4][2];
            #pragma unroll
            for (int nn = 0; nn < 4; ++nn) {
                int n = wn + nn * 8 + gp;
                float b0 = Bs[s][n][kb + kk];
                float b1 = Bs[s][n][kb + kk + 4];
                bh_[nn][0] = f2tf(b0); bl_[nn][0] = __float_as_uint(b0 - __uint_as_float(bh_[nn][0]));
                bh_[nn][1] = f2tf(b1); bl_[nn][1] = __float_as_uint(b1 - __uint_as_float(bh_[nn][1]));
            }

            #pragma unroll
            for (int mm = 0; mm < 2; ++mm) {
                #pragma unroll
                for (int nn = 0; nn < 4; ++nn) {
                    mma_tf32(c[mm][nn], ah[mm], bh_[nn]);
                    mma_tf32(c[mm][nn], ah[mm], bl_[nn]);
                    mma_tf32(c[mm][nn], al[mm], bh_[nn]);
                }
            }
        }

        if (it < DV / BK - 1) {
            ST_TILES(s ^ 1);
            if (it < DV / BK - 2) LD_TILES((it + 2) * BK);
        }
        __syncthreads();
    }

    // epilogue: + bias, write g_h
    #pragma unroll
    for (int mm = 0; mm < 2; ++mm) {
        int m0 = blockIdx.y * 64 + wm + mm * 16 + gp;
        #pragma unroll
        for (int nn = 0; nn < 4; ++nn) {
            int n0 = blockIdx.x * 64 + wn + nn * 8 + kk * 2;
            float2 bv = *(const float2*)(bias + n0);
            float2 r0, r1;
            r0.x = c[mm][nn][0] + bv.x;
            r0.y = c[mm][nn][1] + bv.y;
            r1.x = c[mm][nn][2] + bv.x;
            r1.y = c[mm][nn][3] + bv.y;
            *(float2*)(g_h + (size_t)m0 * DV + n0)       = r0;
            *(float2*)(g_h + (size_t)(m0 + 8) * DV + n0) = r1;
        }
    }
    #undef LD_TILES
    #undef ST_TILES
}

// ---------------------------------------------------------------------------
// Kernel C: LayerNorm + exact GELU + heads. One block (256 thr) per box row.
// ---------------------------------------------------------------------------
__device__ __forceinline__ float warp_sum(float v) {
    v += __shfl_xor_sync(0xffffffff, v, 16);
    v += __shfl_xor_sync(0xffffffff, v, 8);
    v += __shfl_xor_sync(0xffffffff, v, 4);
    v += __shfl_xor_sync(0xffffffff, v, 2);
    v += __shfl_xor_sync(0xffffffff, v, 1);
    return v;
}

__global__ __launch_bounds__(256) void epilogue_kernel(
    const float* __restrict__ ln_g, const float* __restrict__ ln_b,
    const int*   __restrict__ labels,
    const float* __restrict__ Wh, const float* __restrict__ bh,
    const float* __restrict__ Wd, const float* __restrict__ bd,
    float* __restrict__ out)
{
    __shared__ float sred[8];
    __shared__ float red10[10][8];

    const int r    = blockIdx.x;
    const int tid  = threadIdx.x;
    const int lane = tid & 31;
    const int wid  = tid >> 5;
    const int d    = tid * 4;

    float4 hv = *(const float4*)(g_h + (size_t)r * DV + d);

    // mean
    float s = warp_sum(hv.x + hv.y + hv.z + hv.w);
    if (lane == 0) sred[wid] = s;
    __syncthreads();
    float tot = 0.f;
    #pragma unroll
    for (int i = 0; i < 8; ++i) tot += sred[i];
    const float mu = tot * (1.0f / DV);
    __syncthreads();

    // variance (two-pass, centered)
    float cx = hv.x - mu, cy = hv.y - mu, cz = hv.z - mu, cw = hv.w - mu;
    float s2 = warp_sum(cx * cx + cy * cy + cz * cz + cw * cw);
    if (lane == 0) sred[wid] = s2;
    __syncthreads();
    float tot2 = 0.f;
    #pragma unroll
    for (int i = 0; i < 8; ++i) tot2 += sred[i];
    const float rstd = rsqrtf(tot2 * (1.0f / DV) + 1e-5f);

    float4 g4 = *(const float4*)(ln_g + d);
    float4 b4 = *(const float4*)(ln_b + d);
    float4 y4;
    y4.x = cx * rstd * g4.x + b4.x;
    y4.y = cy * rstd * g4.y + b4.y;
    y4.z = cz * rstd * g4.z + b4.z;
    y4.w = cw * rstd * g4.w + b4.w;

    // exact GELU: x * 0.5 * (1 + erf(x / sqrt(2)))
    const float IS2 = 0.70710678118654752f;
    y4.x = y4.x * 0.5f * (1.0f + erff(y4.x * IS2));
    y4.y = y4.y * 0.5f * (1.0f + erff(y4.y * IS2));
    y4.z = y4.z * 0.5f * (1.0f + erff(y4.z * IS2));
    y4.w = y4.w * 0.5f * (1.0f + erff(y4.w * IS2));

    *(float4*)(out + Y_OFF + (size_t)r * DV + d) = y4;

    // heads: 9 attribute dots + 1 discriminator dot
    const int lab  = labels[r];
    const int ncat = c_id2cat[lab];
    const float* whp = Wh + (size_t)lab * MAXATT * DV;

    float p[10];
    #pragma unroll
    for (int k = 0; k < MAXATT; ++k) {
        float4 w4 = *(const float4*)(whp + (size_t)k * DV + d);
        p[k] = y4.x * w4.x + y4.y * w4.y + y4.z * w4.z + y4.w * w4.w;
    }
    {
        float4 w4 = *(const float4*)(Wd + d);
        p[9] = y4.x * w4.x + y4.y * w4.y + y4.z * w4.z + y4.w * w4.w;
    }

    __syncthreads();   // protect sred/red10 reuse ordering
    #pragma unroll
    for (int i = 0; i < 10; ++i) {
        float v = warp_sum(p[i]);
        if (lane == 0) red10[i][wid] = v;
    }
    __syncthreads();

    if (tid < 10) {
        float t2 = 0.f;
        #pragma unroll
        for (int i = 0; i < 8; ++i) t2 += red10[tid][i];
        if (tid < MAXATT) {
            float lv = (tid < ncat) ? (t2 + bh[lab * MAXATT + tid]) : 0.0f;
            out[L_OFF + r * MAXATT + tid] = lv;
        } else {
            out[D_OFF + r] = t2 + bd[0];
        }
    }
}

// ---------------------------------------------------------------------------
extern "C" void kernel_launch(void* const* d_in, const int* in_sizes, int n_in,
                              void* d_out, int out_size)
{
    const float* x      = (const float*)d_in[0];
    const float* boxes  = (const float*)d_in[1];
    const int*   labels = (const int*)  d_in[2];
    const float* W_ff   = (const float*)d_in[3];
    const float* b_ff   = (const float*)d_in[4];
    const float* ln_g   = (const float*)d_in[5];
    const float* ln_b   = (const float*)d_in[6];
    const float* Wh     = (const float*)d_in[7];
    const float* bh     = (const float*)d_in[8];
    const float* Wd     = (const float*)d_in[9];
    const float* bd     = (const float*)d_in[10];
    float* out = (float*)d_out;

    roi_pool_kernel<<<NBOX, 256>>>(x, boxes);

    dim3 gg(DV / 64, NBOX / 64);   // 16 x 8 = 128 blocks
    gemm_tf32_kernel<<<gg, 128>>>(W_ff, b_ff);

    epilogue_kernel<<<NBOX, 256>>>(ln_g, ln_b, labels, Wh, bh, Wd, bd, out);
}

// round 4
// speedup vs baseline: 2.0634x; 1.2351x over previous
#include <cuda_runtime.h>
#include <cuda_bf16.h>
#include <math.h>
#include <stdint.h>

#define BSZ   32
#define NT    196
#define DV    1024
#define NBOX  512
#define GRID_ 14
#define MAXATT 9
#define NLAB  20

#define Y_OFF   0
#define L_OFF   (NBOX * DV)              // 524288
#define D_OFF   (L_OFF + NBOX * MAXATT)  // 528896

__constant__ int c_id2cat[NLAB] = {3,5,2,4,6,3,7,2,5,4,8,3,2,6,5,4,3,9,2,5};

__device__ __nv_bfloat16 g_phi[NBOX * DV];
__device__ __nv_bfloat16 g_plo[NBOX * DV];
__device__ __nv_bfloat16 g_whi[DV * DV];
__device__ __nv_bfloat16 g_wlo[DV * DV];
__device__ float g_h[NBOX * DV];

// ---------------------------------------------------------------------------
// Kernel A: blocks [0,512): ROI max pool -> bf16 hi/lo split.
//           blocks [512,1024): W_ff -> bf16 hi/lo split.
// ---------------------------------------------------------------------------
__global__ __launch_bounds__(256) void pre_kernel(
    const float* __restrict__ x, const float* __restrict__ boxes,
    const float* __restrict__ W)
{
    const int tid = threadIdx.x;

    if (blockIdx.x >= NBOX) {
        // ---- W split: 512 blocks x 256 threads x 8 floats ----
        const int b = blockIdx.x - NBOX;
        const int idx = (b * 256 + tid) * 8;
        float4 v0 = *(const float4*)(W + idx);
        float4 v1 = *(const float4*)(W + idx + 4);
        float v[8] = {v0.x, v0.y, v0.z, v0.w, v1.x, v1.y, v1.z, v1.w};
        uint4 uh, ul;
        __nv_bfloat16* ph = (__nv_bfloat16*)&uh;
        __nv_bfloat16* pl = (__nv_bfloat16*)&ul;
        #pragma unroll
        for (int i = 0; i < 8; ++i) {
            __nv_bfloat16 hi = __float2bfloat16(v[i]);
            ph[i] = hi;
            pl[i] = __float2bfloat16(v[i] - __bfloat162float(hi));
        }
        *(uint4*)(g_whi + idx) = uh;
        *(uint4*)(g_wlo + idx) = ul;
        return;
    }

    // ---- ROI pool ----
    const int n = blockIdx.x;
    const float SC = 14.0f / 224.0f;
    float b0  = boxes[n * 5 + 0];
    float fx1 = boxes[n * 5 + 1];
    float fy1 = boxes[n * 5 + 2];
    float fx2 = boxes[n * 5 + 3];
    float fy2 = boxes[n * 5 + 4];
    int bidx = (int)b0;
    int cx1 = (int)floorf(fx1 * SC + 0.5f);
    int cy1 = (int)floorf(fy1 * SC + 0.5f);
    int cx2 = (int)floorf(fx2 * SC + 0.5f);
    int cy2 = (int)floorf(fy2 * SC + 0.5f);

    int hs = min(max(cy1, 0), GRID_);
    int he = min(max(max(cy2 + 1, cy1 + 1), 0), GRID_);
    int ws = min(max(cx1, 0), GRID_);
    int we = min(max(max(cx2 + 1, cx1 + 1), 0), GRID_);

    float4 mx = make_float4(0.f, 0.f, 0.f, 0.f);
    if (hs < he && ws < we) {
        const float4* xb = (const float4*)(x + (size_t)bidx * NT * DV);
        mx = make_float4(-INFINITY, -INFINITY, -INFINITY, -INFINITY);
        for (int h = hs; h < he; ++h) {
            const float4* rowp = xb + (h * GRID_) * (DV / 4) + tid;
            for (int w = ws; w < we; w += 4) {
                // clamped (duplicate) loads: harmless under max, gives MLP=4
                int w1 = min(w + 1, we - 1);
                int w2 = min(w + 2, we - 1);
                int w3 = min(w + 3, we - 1);
                float4 a = rowp[w  * (DV / 4)];
                float4 b = rowp[w1 * (DV / 4)];
                float4 c = rowp[w2 * (DV / 4)];
                float4 d = rowp[w3 * (DV / 4)];
                mx.x = fmaxf(fmaxf(fmaxf(mx.x, a.x), fmaxf(b.x, c.x)), d.x);
                mx.y = fmaxf(fmaxf(fmaxf(mx.y, a.y), fmaxf(b.y, c.y)), d.y);
                mx.z = fmaxf(fmaxf(fmaxf(mx.z, a.z), fmaxf(b.z, c.z)), d.z);
                mx.w = fmaxf(fmaxf(fmaxf(mx.w, a.w), fmaxf(b.w, c.w)), d.w);
            }
        }
    }

    float v[4] = {mx.x, mx.y, mx.z, mx.w};
    uint2 uh, ul;
    __nv_bfloat16* ph = (__nv_bfloat16*)&uh;
    __nv_bfloat16* pl = (__nv_bfloat16*)&ul;
    #pragma unroll
    for (int i = 0; i < 4; ++i) {
        __nv_bfloat16 hi = __float2bfloat16(v[i]);
        ph[i] = hi;
        pl[i] = __float2bfloat16(v[i] - __bfloat162float(hi));
    }
    *(uint2*)(g_phi + (size_t)n * DV + tid * 4) = uh;
    *(uint2*)(g_plo + (size_t)n * DV + tid * 4) = ul;
}

// ---------------------------------------------------------------------------
// Kernel B: h = pooled @ W^T + bias via bf16 m16n8k16 mma, 3-term split:
//   A_hi*B_hi + A_hi*B_lo + A_lo*B_hi  (fp32 accum)
// 64x64x32 tiles, 128 threads (4 warps 2x2, 32x32 each), cp.async dbl buffer,
// ldmatrix.x4 frag loads, smem stride 40 bf16 (80B = 5x16B, conflict-free).
// ---------------------------------------------------------------------------
#define SST 40

__device__ __forceinline__ void ldsm4(uint32_t r[4], uint32_t addr) {
    asm volatile("ldmatrix.sync.aligned.m8n8.x4.shared.b16 {%0,%1,%2,%3}, [%4];"
                 : "=r"(r[0]), "=r"(r[1]), "=r"(r[2]), "=r"(r[3]) : "r"(addr));
}

__device__ __forceinline__ void mma_bf16(float c[4], const uint32_t a[4],
                                         uint32_t b0, uint32_t b1) {
    asm volatile(
        "mma.sync.aligned.m16n8k16.row.col.f32.bf16.bf16.f32 "
        "{%0,%1,%2,%3}, {%4,%5,%6,%7}, {%8,%9}, {%0,%1,%2,%3};\n"
        : "+f"(c[0]), "+f"(c[1]), "+f"(c[2]), "+f"(c[3])
        : "r"(a[0]), "r"(a[1]), "r"(a[2]), "r"(a[3]), "r"(b0), "r"(b1));
}

__device__ __forceinline__ void cpa16(uint32_t dst, const void* src) {
    asm volatile("cp.async.cg.shared.global [%0], [%1], 16;" :: "r"(dst), "l"(src));
}

__global__ __launch_bounds__(128) void gemm_bf16_kernel(const float* __restrict__ bias)
{
    __shared__ __align__(16) __nv_bfloat16 Ah[2][64][SST];
    __shared__ __align__(16) __nv_bfloat16 Al[2][64][SST];
    __shared__ __align__(16) __nv_bfloat16 Bh[2][64][SST];
    __shared__ __align__(16) __nv_bfloat16 Bl[2][64][SST];

    const int tid  = threadIdx.x;
    const int lane = tid & 31;
    const int wid  = tid >> 5;
    const int wm   = (wid & 1) * 32;
    const int wn   = (wid >> 1) * 32;

    const __nv_bfloat16* Agh = g_phi + (size_t)(blockIdx.y * 64) * DV;
    const __nv_bfloat16* Agl = g_plo + (size_t)(blockIdx.y * 64) * DV;
    const __nv_bfloat16* Bgh = g_whi + (size_t)(blockIdx.x * 64) * DV;
    const __nv_bfloat16* Bgl = g_wlo + (size_t)(blockIdx.x * 64) * DV;

    const int lr0 = tid >> 2;              // rows 0..31
    const int lkq = (tid & 3) * 8;         // k offset 0,8,16,24

    // ldmatrix lane addressing
    const int arow = (lane & 15);
    const int akh  = (lane >> 4) * 8;
    const int brow = (lane & 7) + ((lane >> 4) << 3);
    const int bkh  = ((lane >> 3) & 1) * 8;

    float c[2][4][4] = {};

    #define ISSUE(S, K0)                                                        \
    {                                                                           \
        cpa16((uint32_t)__cvta_generic_to_shared(&Ah[S][lr0][lkq]),             \
              Agh + (size_t)lr0 * DV + (K0) + lkq);                             \
        cpa16((uint32_t)__cvta_generic_to_shared(&Al[S][lr0][lkq]),             \
              Agl + (size_t)lr0 * DV + (K0) + lkq);                             \
        cpa16((uint32_t)__cvta_generic_to_shared(&Bh[S][lr0][lkq]),             \
              Bgh + (size_t)lr0 * DV + (K0) + lkq);                             \
        cpa16((uint32_t)__cvta_generic_to_shared(&Bl[S][lr0][lkq]),             \
              Bgl + (size_t)lr0 * DV + (K0) + lkq);                             \
        cpa16((uint32_t)__cvta_generic_to_shared(&Ah[S][lr0 + 32][lkq]),        \
              Agh + (size_t)(lr0 + 32) * DV + (K0) + lkq);                      \
        cpa16((uint32_t)__cvta_generic_to_shared(&Al[S][lr0 + 32][lkq]),        \
              Agl + (size_t)(lr0 + 32) * DV + (K0) + lkq);                      \
        cpa16((uint32_t)__cvta_generic_to_shared(&Bh[S][lr0 + 32][lkq]),        \
              Bgh + (size_t)(lr0 + 32) * DV + (K0) + lkq);                      \
        cpa16((uint32_t)__cvta_generic_to_shared(&Bl[S][lr0 + 32][lkq]),        \
              Bgl + (size_t)(lr0 + 32) * DV + (K0) + lkq);                      \
    }

    ISSUE(0, 0);
    asm volatile("cp.async.commit_group;");
    ISSUE(1, 32);
    asm volatile("cp.async.commit_group;");

    for (int it = 0; it < DV / 32; ++it) {
        const int s = it & 1;
        asm volatile("cp.async.wait_group 1;");
        __syncthreads();

        #pragma unroll
        for (int kc2 = 0; kc2 < 2; ++kc2) {
            const int kc = kc2 * 16;
            uint32_t ah[2][4], al_[2][4], bh_[2][4], bl_[2][4];
            #pragma unroll
            for (int ms = 0; ms < 2; ++ms) {
                ldsm4(ah[ms], (uint32_t)__cvta_generic_to_shared(
                          &Ah[s][wm + ms * 16 + arow][kc + akh]));
                ldsm4(al_[ms], (uint32_t)__cvta_generic_to_shared(
                          &Al[s][wm + ms * 16 + arow][kc + akh]));
            }
            #pragma unroll
            for (int np = 0; np < 2; ++np) {
                ldsm4(bh_[np], (uint32_t)__cvta_generic_to_shared(
                          &Bh[s][wn + np * 16 + brow][kc + bkh]));
                ldsm4(bl_[np], (uint32_t)__cvta_generic_to_shared(
                          &Bl[s][wn + np * 16 + brow][kc + bkh]));
            }
            #pragma unroll
            for (int ms = 0; ms < 2; ++ms) {
                #pragma unroll
                for (int np = 0; np < 2; ++np) {
                    mma_bf16(c[ms][2 * np],     ah[ms],  bh_[np][0], bh_[np][1]);
                    mma_bf16(c[ms][2 * np + 1], ah[ms],  bh_[np][2], bh_[np][3]);
                    mma_bf16(c[ms][2 * np],     ah[ms],  bl_[np][0], bl_[np][1]);
                    mma_bf16(c[ms][2 * np + 1], ah[ms],  bl_[np][2], bl_[np][3]);
                    mma_bf16(c[ms][2 * np],     al_[ms], bh_[np][0], bh_[np][1]);
                    mma_bf16(c[ms][2 * np + 1], al_[ms], bh_[np][2], bh_[np][3]);
                }
            }
        }

        __syncthreads();
        if (it + 2 < DV / 32) { ISSUE(s, (it + 2) * 32); }
        asm volatile("cp.async.commit_group;");
    }
    #undef ISSUE

    const int g   = lane >> 2;
    const int tig = lane & 3;
    #pragma unroll
    for (int ms = 0; ms < 2; ++ms) {
        const int m0 = blockIdx.y * 64 + wm + ms * 16 + g;
        #pragma unroll
        for (int ns = 0; ns < 4; ++ns) {
            const int n0 = blockIdx.x * 64 + wn + ns * 8 + tig * 2;
            float2 bv = *(const float2*)(bias + n0);
            float2 r0, r1;
            r0.x = c[ms][ns][0] + bv.x;
            r0.y = c[ms][ns][1] + bv.y;
            r1.x = c[ms][ns][2] + bv.x;
            r1.y = c[ms][ns][3] + bv.y;
            *(float2*)(g_h + (size_t)m0 * DV + n0)       = r0;
            *(float2*)(g_h + (size_t)(m0 + 8) * DV + n0) = r1;
        }
    }
}

// ---------------------------------------------------------------------------
// Kernel C: LayerNorm + exact GELU + heads. One block (256 thr) per box row.
// ---------------------------------------------------------------------------
__device__ __forceinline__ float warp_sum(float v) {
    v += __shfl_xor_sync(0xffffffff, v, 16);
    v += __shfl_xor_sync(0xffffffff, v, 8);
    v += __shfl_xor_sync(0xffffffff, v, 4);
    v += __shfl_xor_sync(0xffffffff, v, 2);
    v += __shfl_xor_sync(0xffffffff, v, 1);
    return v;
}

__global__ __launch_bounds__(256) void epilogue_kernel(
    const float* __restrict__ ln_g, const float* __restrict__ ln_b,
    const int*   __restrict__ labels,
    const float* __restrict__ Wh, const float* __restrict__ bh,
    const float* __restrict__ Wd, const float* __restrict__ bd,
    float* __restrict__ out)
{
    __shared__ float sred[8];
    __shared__ float red10[10][8];

    const int r    = blockIdx.x;
    const int tid  = threadIdx.x;
    const int lane = tid & 31;
    const int wid  = tid >> 5;
    const int d    = tid * 4;

    float4 hv = *(const float4*)(g_h + (size_t)r * DV + d);

    float s = warp_sum(hv.x + hv.y + hv.z + hv.w);
    if (lane == 0) sred[wid] = s;
    __syncthreads();
    float tot = 0.f;
    #pragma unroll
    for (int i = 0; i < 8; ++i) tot += sred[i];
    const float mu = tot * (1.0f / DV);
    __syncthreads();

    float cx = hv.x - mu, cy = hv.y - mu, cz = hv.z - mu, cw = hv.w - mu;
    float s2 = warp_sum(cx * cx + cy * cy + cz * cz + cw * cw);
    if (lane == 0) sred[wid] = s2;
    __syncthreads();
    float tot2 = 0.f;
    #pragma unroll
    for (int i = 0; i < 8; ++i) tot2 += sred[i];
    const float rstd = rsqrtf(tot2 * (1.0f / DV) + 1e-5f);

    float4 g4 = *(const float4*)(ln_g + d);
    float4 b4 = *(const float4*)(ln_b + d);
    float4 y4;
    y4.x = cx * rstd * g4.x + b4.x;
    y4.y = cy * rstd * g4.y + b4.y;
    y4.z = cz * rstd * g4.z + b4.z;
    y4.w = cw * rstd * g4.w + b4.w;

    const float IS2 = 0.70710678118654752f;
    y4.x = y4.x * 0.5f * (1.0f + erff(y4.x * IS2));
    y4.y = y4.y * 0.5f * (1.0f + erff(y4.y * IS2));
    y4.z = y4.z * 0.5f * (1.0f + erff(y4.z * IS2));
    y4.w = y4.w * 0.5f * (1.0f + erff(y4.w * IS2));

    *(float4*)(out + Y_OFF + (size_t)r * DV + d) = y4;

    const int lab  = labels[r];
    const int ncat = c_id2cat[lab];
    const float* whp = Wh + (size_t)lab * MAXATT * DV;

    float p[10];
    #pragma unroll
    for (int k = 0; k < MAXATT; ++k) {
        float4 w4 = *(const float4*)(whp + (size_t)k * DV + d);
        p[k] = y4.x * w4.x + y4.y * w4.y + y4.z * w4.z + y4.w * w4.w;
    }
    {
        float4 w4 = *(const float4*)(Wd + d);
        p[9] = y4.x * w4.x + y4.y * w4.y + y4.z * w4.z + y4.w * w4.w;
    }

    __syncthreads();
    #pragma unroll
    for (int i = 0; i < 10; ++i) {
        float v = warp_sum(p[i]);
        if (lane == 0) red10[i][wid] = v;
    }
    __syncthreads();

    if (tid < 10) {
        float t2 = 0.f;
        #pragma unroll
        for (int i = 0; i < 8; ++i) t2 += red10[tid][i];
        if (tid < MAXATT) {
            float lv = (tid < ncat) ? (t2 + bh[lab * MAXATT + tid]) : 0.0f;
            out[L_OFF + r * MAXATT + tid] = lv;
        } else {
            out[D_OFF + r] = t2 + bd[0];
        }
    }
}

// ---------------------------------------------------------------------------
extern "C" void kernel_launch(void* const* d_in, const int* in_sizes, int n_in,
                              void* d_out, int out_size)
{
    const float* x      = (const float*)d_in[0];
    const float* boxes  = (const float*)d_in[1];
    const int*   labels = (const int*)  d_in[2];
    const float* W_ff   = (const float*)d_in[3];
    const float* b_ff   = (const float*)d_in[4];
    const float* ln_g   = (const float*)d_in[5];
    const float* ln_b   = (const float*)d_in[6];
    const float* Wh     = (const float*)d_in[7];
    const float* bh     = (const float*)d_in[8];
    const float* Wd     = (const float*)d_in[9];
    const float* bd     = (const float*)d_in[10];
    float* out = (float*)d_out;

    pre_kernel<<<NBOX + 512, 256>>>(x, boxes, W_ff);

    dim3 gg(DV / 64, NBOX / 64);   // 16 x 8 = 128 blocks
    gemm_bf16_kernel<<<gg, 128>>>(b_ff);

    epilogue_kernel<<<NBOX, 256>>>(ln_g, ln_b, labels, Wh, bh, Wd, bd, out);
}

// round 6
// speedup vs baseline: 2.0653x; 1.0009x over previous
#include <cuda_runtime.h>
#include <cuda_bf16.h>
#include <math.h>
#include <stdint.h>

#define BSZ   32
#define NT    196
#define DV    1024
#define NBOX  512
#define GRID_ 14
#define MAXATT 9
#define NLAB  20

#define Y_OFF   0
#define L_OFF   (NBOX * DV)              // 524288
#define D_OFF   (L_OFF + NBOX * MAXATT)  // 528896

__constant__ int c_id2cat[NLAB] = {3,5,2,4,6,3,7,2,5,4,8,3,2,6,5,4,3,9,2,5};

__device__ __nv_bfloat16 g_phi[NBOX * DV];
__device__ __nv_bfloat16 g_plo[NBOX * DV];
__device__ __nv_bfloat16 g_whi[DV * DV];
__device__ __nv_bfloat16 g_wlo[DV * DV];
__device__ float g_h[NBOX * DV];

// ---------------------------------------------------------------------------
// Kernel A: blocks [0,512): ROI max pool -> bf16 hi/lo split.
//           blocks [512,1024): W_ff -> bf16 hi/lo split.
// ---------------------------------------------------------------------------
__global__ __launch_bounds__(256) void pre_kernel(
    const float* __restrict__ x, const float* __restrict__ boxes,
    const float* __restrict__ W)
{
    const int tid = threadIdx.x;

    if (blockIdx.x >= NBOX) {
        const int b = blockIdx.x - NBOX;
        const int idx = (b * 256 + tid) * 8;
        float4 v0 = *(const float4*)(W + idx);
        float4 v1 = *(const float4*)(W + idx + 4);
        float v[8] = {v0.x, v0.y, v0.z, v0.w, v1.x, v1.y, v1.z, v1.w};
        uint4 uh, ul;
        __nv_bfloat16* ph = (__nv_bfloat16*)&uh;
        __nv_bfloat16* pl = (__nv_bfloat16*)&ul;
        #pragma unroll
        for (int i = 0; i < 8; ++i) {
            __nv_bfloat16 hi = __float2bfloat16(v[i]);
            ph[i] = hi;
            pl[i] = __float2bfloat16(v[i] - __bfloat162float(hi));
        }
        *(uint4*)(g_whi + idx) = uh;
        *(uint4*)(g_wlo + idx) = ul;
        return;
    }

    const int n = blockIdx.x;
    const float SC = 14.0f / 224.0f;
    float b0  = boxes[n * 5 + 0];
    float fx1 = boxes[n * 5 + 1];
    float fy1 = boxes[n * 5 + 2];
    float fx2 = boxes[n * 5 + 3];
    float fy2 = boxes[n * 5 + 4];
    int bidx = (int)b0;
    int cx1 = (int)floorf(fx1 * SC + 0.5f);
    int cy1 = (int)floorf(fy1 * SC + 0.5f);
    int cx2 = (int)floorf(fx2 * SC + 0.5f);
    int cy2 = (int)floorf(fy2 * SC + 0.5f);

    int hs = min(max(cy1, 0), GRID_);
    int he = min(max(max(cy2 + 1, cy1 + 1), 0), GRID_);
    int ws = min(max(cx1, 0), GRID_);
    int we = min(max(max(cx2 + 1, cx1 + 1), 0), GRID_);

    float4 mx = make_float4(0.f, 0.f, 0.f, 0.f);
    if (hs < he && ws < we) {
        const float4* xb = (const float4*)(x + (size_t)bidx * NT * DV);
        mx = make_float4(-INFINITY, -INFINITY, -INFINITY, -INFINITY);
        for (int h = hs; h < he; h += 2) {
            int h1 = min(h + 1, he - 1);
            const float4* r0 = xb + (h  * GRID_) * (DV / 4) + tid;
            const float4* r1 = xb + (h1 * GRID_) * (DV / 4) + tid;
            for (int w = ws; w < we; w += 2) {
                // clamped duplicate loads: harmless under max, MLP=4..8
                int w1 = min(w + 1, we - 1);
                float4 a = r0[w  * (DV / 4)];
                float4 b = r0[w1 * (DV / 4)];
                float4 c = r1[w  * (DV / 4)];
                float4 d = r1[w1 * (DV / 4)];
                mx.x = fmaxf(fmaxf(fmaxf(mx.x, a.x), fmaxf(b.x, c.x)), d.x);
                mx.y = fmaxf(fmaxf(fmaxf(mx.y, a.y), fmaxf(b.y, c.y)), d.y);
                mx.z = fmaxf(fmaxf(fmaxf(mx.z, a.z), fmaxf(b.z, c.z)), d.z);
                mx.w = fmaxf(fmaxf(fmaxf(mx.w, a.w), fmaxf(b.w, c.w)), d.w);
            }
        }
    }

    float v[4] = {mx.x, mx.y, mx.z, mx.w};
    uint2 uh, ul;
    __nv_bfloat16* ph = (__nv_bfloat16*)&uh;
    __nv_bfloat16* pl = (__nv_bfloat16*)&ul;
    #pragma unroll
    for (int i = 0; i < 4; ++i) {
        __nv_bfloat16 hi = __float2bfloat16(v[i]);
        ph[i] = hi;
        pl[i] = __float2bfloat16(v[i] - __bfloat162float(hi));
    }
    *(uint2*)(g_phi + (size_t)n * DV + tid * 4) = uh;
    *(uint2*)(g_plo + (size_t)n * DV + tid * 4) = ul;
}

// ---------------------------------------------------------------------------
// Kernel B: h = pooled @ W^T + bias via bf16 m16n8k16 mma, 3-term split:
//   A_hi*B_hi + A_hi*B_lo + A_lo*B_hi  (fp32 accum)
// 64x64x32 tiles, 256 threads (8 warps, 2 per SMSP, 32x16 warp tiles),
// cp.async double buffer, ldmatrix.x4 frag loads, smem stride 40 bf16.
// ---------------------------------------------------------------------------
#define SST 40

__device__ __forceinline__ void ldsm4(uint32_t r[4], uint32_t addr) {
    asm volatile("ldmatrix.sync.aligned.m8n8.x4.shared.b16 {%0,%1,%2,%3}, [%4];"
                 : "=r"(r[0]), "=r"(r[1]), "=r"(r[2]), "=r"(r[3]) : "r"(addr));
}

__device__ __forceinline__ void mma_bf16(float c[4], const uint32_t a[4],
                                         uint32_t b0, uint32_t b1) {
    asm volatile(
        "mma.sync.aligned.m16n8k16.row.col.f32.bf16.bf16.f32 "
        "{%0,%1,%2,%3}, {%4,%5,%6,%7}, {%8,%9}, {%0,%1,%2,%3};\n"
        : "+f"(c[0]), "+f"(c[1]), "+f"(c[2]), "+f"(c[3])
        : "r"(a[0]), "r"(a[1]), "r"(a[2]), "r"(a[3]), "r"(b0), "r"(b1));
}

__device__ __forceinline__ void cpa16(uint32_t dst, const void* src) {
    asm volatile("cp.async.cg.shared.global [%0], [%1], 16;" :: "r"(dst), "l"(src));
}

__global__ __launch_bounds__(256) void gemm_bf16_kernel(const float* __restrict__ bias)
{
    __shared__ __align__(16) __nv_bfloat16 Ah[2][64][SST];
    __shared__ __align__(16) __nv_bfloat16 Al[2][64][SST];
    __shared__ __align__(16) __nv_bfloat16 Bh[2][64][SST];
    __shared__ __align__(16) __nv_bfloat16 Bl[2][64][SST];

    const int tid  = threadIdx.x;
    const int lane = tid & 31;
    const int wid  = tid >> 5;
    const int wm   = (wid & 1) * 32;    // warp M offset (2 warps in M)
    const int wn   = (wid >> 1) * 16;   // warp N offset (4 warps in N)

    const __nv_bfloat16* Agh = g_phi + (size_t)(blockIdx.y * 64) * DV;
    const __nv_bfloat16* Agl = g_plo + (size_t)(blockIdx.y * 64) * DV;
    const __nv_bfloat16* Bgh = g_whi + (size_t)(blockIdx.x * 64) * DV;
    const __nv_bfloat16* Bgl = g_wlo + (size_t)(blockIdx.x * 64) * DV;

    const int lr0 = tid >> 2;              // rows 0..63
    const int lkq = (tid & 3) * 8;         // k offset 0,8,16,24

    // ldmatrix lane addressing
    const int arow = (lane & 15);
    const int akh  = (lane >> 4) * 8;
    const int brow = (lane & 7) + ((lane >> 4) << 3);
    const int bkh  = ((lane >> 3) & 1) * 8;

    float c[2][2][4] = {};

    #define ISSUE(S, K0)                                                        \
    {                                                                           \
        cpa16((uint32_t)__cvta_generic_to_shared(&Ah[S][lr0][lkq]),             \
              Agh + (size_t)lr0 * DV + (K0) + lkq);                             \
        cpa16((uint32_t)__cvta_generic_to_shared(&Al[S][lr0][lkq]),             \
              Agl + (size_t)lr0 * DV + (K0) + lkq);                             \
        cpa16((uint32_t)__cvta_generic_to_shared(&Bh[S][lr0][lkq]),             \
              Bgh + (size_t)lr0 * DV + (K0) + lkq);                             \
        cpa16((uint32_t)__cvta_generic_to_shared(&Bl[S][lr0][lkq]),             \
              Bgl + (size_t)lr0 * DV + (K0) + lkq);                             \
    }

    ISSUE(0, 0);
    asm volatile("cp.async.commit_group;");
    ISSUE(1, 32);
    asm volatile("cp.async.commit_group;");

    for (int it = 0; it < DV / 32; ++it) {
        const int s = it & 1;
        asm volatile("cp.async.wait_group 1;");
        __syncthreads();

        #pragma unroll
        for (int kc2 = 0; kc2 < 2; ++kc2) {
            const int kc = kc2 * 16;
            uint32_t ah[2][4], al_[2][4], bh_[4], bl_[4];
            #pragma unroll
            for (int ms = 0; ms < 2; ++ms) {
                ldsm4(ah[ms], (uint32_t)__cvta_generic_to_shared(
                          &Ah[s][wm + ms * 16 + arow][kc + akh]));
                ldsm4(al_[ms], (uint32_t)__cvta_generic_to_shared(
                          &Al[s][wm + ms * 16 + arow][kc + akh]));
            }
            ldsm4(bh_, (uint32_t)__cvta_generic_to_shared(
                      &Bh[s][wn + brow][kc + bkh]));
            ldsm4(bl_, (uint32_t)__cvta_generic_to_shared(
                      &Bl[s][wn + brow][kc + bkh]));
            #pragma unroll
            for (int ms = 0; ms < 2; ++ms) {
                mma_bf16(c[ms][0], ah[ms],  bh_[0], bh_[1]);
                mma_bf16(c[ms][1], ah[ms],  bh_[2], bh_[3]);
                mma_bf16(c[ms][0], ah[ms],  bl_[0], bl_[1]);
                mma_bf16(c[ms][1], ah[ms],  bl_[2], bl_[3]);
                mma_bf16(c[ms][0], al_[ms], bh_[0], bh_[1]);
                mma_bf16(c[ms][1], al_[ms], bh_[2], bh_[3]);
            }
        }

        __syncthreads();
        if (it + 2 < DV / 32) { ISSUE(s, (it + 2) * 32); }
        asm volatile("cp.async.commit_group;");
    }
    #undef ISSUE

    const int g   = lane >> 2;
    const int tig = lane & 3;
    #pragma unroll
    for (int ms = 0; ms < 2; ++ms) {
        const int m0 = blockIdx.y * 64 + wm + ms * 16 + g;
        #pragma unroll
        for (int ns = 0; ns < 2; ++ns) {
            const int n0 = blockIdx.x * 64 + wn + ns * 8 + tig * 2;
            float2 bv = *(const float2*)(bias + n0);
            float2 r0, r1;
            r0.x = c[ms][ns][0] + bv.x;
            r0.y = c[ms][ns][1] + bv.y;
            r1.x = c[ms][ns][2] + bv.x;
            r1.y = c[ms][ns][3] + bv.y;
            *(float2*)(g_h + (size_t)m0 * DV + n0)       = r0;
            *(float2*)(g_h + (size_t)(m0 + 8) * DV + n0) = r1;
        }
    }
}

// ---------------------------------------------------------------------------
// Kernel C: LayerNorm + exact GELU + heads. One block (256 thr) per box row.
// ---------------------------------------------------------------------------
__device__ __forceinline__ float warp_sum(float v) {
    v += __shfl_xor_sync(0xffffffff, v, 16);
    v += __shfl_xor_sync(0xffffffff, v, 8);
    v += __shfl_xor_sync(0xffffffff, v, 4);
    v += __shfl_xor_sync(0xffffffff, v, 2);
    v += __shfl_xor_sync(0xffffffff, v, 1);
    return v;
}

__global__ __launch_bounds__(256) void epilogue_kernel(
    const float* __restrict__ ln_g, const float* __restrict__ ln_b,
    const int*   __restrict__ labels,
    const float* __restrict__ Wh, const float* __restrict__ bh,
    const float* __restrict__ Wd, const float* __restrict__ bd,
    float* __restrict__ out)
{
    __shared__ float sred[8];
    __shared__ float red10[10][8];

    const int r    = blockIdx.x;
    const int tid  = threadIdx.x;
    const int lane = tid & 31;
    const int wid  = tid >> 5;
    const int d    = tid * 4;

    float4 hv = *(const float4*)(g_h + (size_t)r * DV + d);

    float s = warp_sum(hv.x + hv.y + hv.z + hv.w);
    if (lane == 0) sred[wid] = s;
    __syncthreads();
    float tot = 0.f;
    #pragma unroll
    for (int i = 0; i < 8; ++i) tot += sred[i];
    const float mu = tot * (1.0f / DV);
    __syncthreads();

    float cx = hv.x - mu, cy = hv.y - mu, cz = hv.z - mu, cw = hv.w - mu;
    float s2 = warp_sum(cx * cx + cy * cy + cz * cz + cw * cw);
    if (lane == 0) sred[wid] = s2;
    __syncthreads();
    float tot2 = 0.f;
    #pragma unroll
    for (int i = 0; i < 8; ++i) tot2 += sred[i];
    const float rstd = rsqrtf(tot2 * (1.0f / DV) + 1e-5f);

    float4 g4 = *(const float4*)(ln_g + d);
    float4 b4 = *(const float4*)(ln_b + d);
    float4 y4;
    y4.x = cx * rstd * g4.x + b4.x;
    y4.y = cy * rstd * g4.y + b4.y;
    y4.z = cz * rstd * g4.z + b4.z;
    y4.w = cw * rstd * g4.w + b4.w;

    const float IS2 = 0.70710678118654752f;
    y4.x = y4.x * 0.5f * (1.0f + erff(y4.x * IS2));
    y4.y = y4.y * 0.5f * (1.0f + erff(y4.y * IS2));
    y4.z = y4.z * 0.5f * (1.0f + erff(y4.z * IS2));
    y4.w = y4.w * 0.5f * (1.0f + erff(y4.w * IS2));

    *(float4*)(out + Y_OFF + (size_t)r * DV + d) = y4;

    const int lab  = labels[r];
    const int ncat = c_id2cat[lab];
    const float* whp = Wh + (size_t)lab * MAXATT * DV;

    float p[10];
    #pragma unroll
    for (int k = 0; k < MAXATT; ++k) {
        float4 w4 = *(const float4*)(whp + (size_t)k * DV + d);
        p[k] = y4.x * w4.x + y4.y * w4.y + y4.z * w4.z + y4.w * w4.w;
    }
    {
        float4 w4 = *(const float4*)(Wd + d);
        p[9] = y4.x * w4.x + y4.y * w4.y + y4.z * w4.z + y4.w * w4.w;
    }

    __syncthreads();
    #pragma unroll
    for (int i = 0; i < 10; ++i) {
        float v = warp_sum(p[i]);
        if (lane == 0) red10[i][wid] = v;
    }
    __syncthreads();

    if (tid < 10) {
        float t2 = 0.f;
        #pragma unroll
        for (int i = 0; i < 8; ++i) t2 += red10[tid][i];
        if (tid < MAXATT) {
            float lv = (tid < ncat) ? (t2 + bh[lab * MAXATT + tid]) : 0.0f;
            out[L_OFF + r * MAXATT + tid] = lv;
        } else {
            out[D_OFF + r] = t2 + bd[0];
        }
    }
}

// ---------------------------------------------------------------------------
extern "C" void kernel_launch(void* const* d_in, const int* in_sizes, int n_in,
                              void* d_out, int out_size)
{
    const float* x      = (const float*)d_in[0];
    const float* boxes  = (const float*)d_in[1];
    const int*   labels = (const int*)  d_in[2];
    const float* W_ff   = (const float*)d_in[3];
    const float* b_ff   = (const float*)d_in[4];
    const float* ln_g   = (const float*)d_in[5];
    const float* ln_b   = (const float*)d_in[6];
    const float* Wh     = (const float*)d_in[7];
    const float* bh     = (const float*)d_in[8];
    const float* Wd     = (const float*)d_in[9];
    const float* bd     = (const float*)d_in[10];
    float* out = (float*)d_out;

    pre_kernel<<<NBOX + 512, 256>>>(x, boxes, W_ff);

    dim3 gg(DV / 64, NBOX / 64);   // 16 x 8 = 128 blocks
    gemm_bf16_kernel<<<gg, 256>>>(b_ff);

    epilogue_kernel<<<NBOX, 256>>>(ln_g, ln_b, labels, Wh, bh, Wd, bd, out);
}